// round 2
// baseline (speedup 1.0000x reference)
#include <cuda_runtime.h>

#define NPTS 1024
#define HID  256
#define XD   128

#define TJ   64          // j-tile (xp rows)
#define TI   32          // i-tile (ypb rows)
#define SWID 260         // padded smem row stride (floats): 1040B, 1040%128=16 -> conflict-free strided access
#define SMEM_BYTES (((TJ + TI) * SWID + 256) * 4)

// ---- device scratch (static: no runtime allocation allowed) ----
__device__ float g_xp [NPTS * HID];   // x @ Wx
__device__ float g_ypb[NPTS * HID];   // y @ Wy + b1
__device__ float g_pexp [512];
__device__ float g_pdiag[512];

// packed f32x2: z = a + c; r = relu(z); acc = r * w + acc   (2 elements per invocation)
#define RELU_DOT(ACC, A, C, W)                         \
  asm("{\n\t"                                          \
      ".reg .b64 zz, rr;\n\t"                          \
      ".reg .f32 zl, zh, rl, rh;\n\t"                  \
      "add.rn.f32x2 zz, %1, %2;\n\t"                   \
      "mov.b64 {zl, zh}, zz;\n\t"                      \
      "max.f32 rl, zl, 0f00000000;\n\t"                \
      "max.f32 rh, zh, 0f00000000;\n\t"                \
      "mov.b64 rr, {rl, rh};\n\t"                      \
      "fma.rn.f32x2 %0, rr, %3, %0;\n\t"               \
      "}" : "+l"(ACC) : "l"(A), "l"(C), "l"(W))

// ---------------- prologue: xp = x @ W1[:128], ypb = y @ W1[128:] + b1 ----------------
__global__ void __launch_bounds__(256) prologue_kernel(
    const float* __restrict__ x, const float* __restrict__ y,
    const float* __restrict__ W1, const float* __restrict__ b1)
{
  __shared__ float sx[16 * 128];
  const int which = blockIdx.y;                // 0: x-path, 1: y-path
  const float* src = which ? y : x;
  const int r0 = blockIdx.x * 16;
  const int tid = threadIdx.x;

  // load 16x128 input tile (contiguous)
  const float4* s4 = reinterpret_cast<const float4*>(src + r0 * XD);
  for (int t = tid; t < 16 * 128 / 4; t += 256)
    reinterpret_cast<float4*>(sx)[t] = s4[t];
  __syncthreads();

  const int c = tid;                            // output column 0..255
  const float* Wp = W1 + (which ? (XD * HID) : 0) + c;
  float acc[16];
#pragma unroll
  for (int r = 0; r < 16; r++) acc[r] = 0.0f;

  for (int m = 0; m < XD; m += 4) {
    const float w0 = Wp[(m + 0) * HID];
    const float w1 = Wp[(m + 1) * HID];
    const float w2 = Wp[(m + 2) * HID];
    const float w3 = Wp[(m + 3) * HID];
#pragma unroll
    for (int r = 0; r < 16; r++) {
      const float4 xv = *reinterpret_cast<const float4*>(&sx[r * 128 + m]);
      acc[r] = fmaf(xv.x, w0, acc[r]);
      acc[r] = fmaf(xv.y, w1, acc[r]);
      acc[r] = fmaf(xv.z, w2, acc[r]);
      acc[r] = fmaf(xv.w, w3, acc[r]);
    }
  }

  const float bias = which ? b1[c] : 0.0f;
  float* dst = which ? g_ypb : g_xp;
#pragma unroll
  for (int r = 0; r < 16; r++) dst[(r0 + r) * HID + c] = acc[r] + bias;
}

// ---------------- main pairwise kernel ----------------
// grid: (16 j-tiles, 32 i-tiles); block: 256 threads; thread microtile: 4 j x 2 i (strided by 16)
__global__ void __launch_bounds__(256, 2) pair_kernel(
    const float* __restrict__ W2, const float* __restrict__ b2)
{
  extern __shared__ float sm[];
  float* sa = sm;                       // TJ x SWID (xp rows)
  float* sc = sm + TJ * SWID;           // TI x SWID (ypb rows)
  float* sw = sm + (TJ + TI) * SWID;    // 256 (W2; later reused as reduce buffer)

  const int tid = threadIdx.x;
  const int bj = blockIdx.x, bi = blockIdx.y;
  const int jbase = bj * TJ, ibase = bi * TI;

  {
    const float4* src = reinterpret_cast<const float4*>(&g_xp[jbase * HID]);
    for (int t = tid; t < TJ * (HID / 4); t += 256) {
      const int r = t >> 6, c4 = t & 63;
      *reinterpret_cast<float4*>(&sa[r * SWID + c4 * 4]) = src[r * 64 + c4];
    }
  }
  {
    const float4* src = reinterpret_cast<const float4*>(&g_ypb[ibase * HID]);
    for (int t = tid; t < TI * (HID / 4); t += 256) {
      const int r = t >> 6, c4 = t & 63;
      *reinterpret_cast<float4*>(&sc[r * SWID + c4 * 4]) = src[r * 64 + c4];
    }
  }
  sw[tid] = W2[tid];
  __syncthreads();

  const int tx = tid & 15;    // j direction
  const int ty = tid >> 4;    // i direction

  unsigned long long acc[8];
#pragma unroll
  for (int p = 0; p < 8; p++) acc[p] = 0ull;

#pragma unroll 4
  for (int k = 0; k < HID; k += 4) {
    const ulonglong2 wv = *reinterpret_cast<const ulonglong2*>(&sw[k]);
    ulonglong2 av[4], cv[2];
#pragma unroll
    for (int jj = 0; jj < 4; jj++)
      av[jj] = *reinterpret_cast<const ulonglong2*>(&sa[(tx + 16 * jj) * SWID + k]);
#pragma unroll
    for (int ii = 0; ii < 2; ii++)
      cv[ii] = *reinterpret_cast<const ulonglong2*>(&sc[(ty + 16 * ii) * SWID + k]);
#pragma unroll
    for (int ii = 0; ii < 2; ii++)
#pragma unroll
      for (int jj = 0; jj < 4; jj++) {
        RELU_DOT(acc[ii * 4 + jj], av[jj].x, cv[ii].x, wv.x);
        RELU_DOT(acc[ii * 4 + jj], av[jj].y, cv[ii].y, wv.y);
      }
  }

  const float b2v = __ldg(b2);
  float eacc = 0.0f, dacc = 0.0f;
#pragma unroll
  for (int ii = 0; ii < 2; ii++)
#pragma unroll
    for (int jj = 0; jj < 4; jj++) {
      union { unsigned long long u; float2 f; } uu;
      uu.u = acc[ii * 4 + jj];
      const float t = uu.f.x + uu.f.y + b2v;
      eacc += __expf(t - 1.0f);
      const int gi = ibase + ty + 16 * ii;
      const int gj = jbase + tx + 16 * jj;
      if (gi == gj) dacc += t;
    }

  // block reductions (reuse sw)
  __syncthreads();
  sw[tid] = eacc;
  __syncthreads();
  for (int s = 128; s > 0; s >>= 1) {
    if (tid < s) sw[tid] += sw[tid + s];
    __syncthreads();
  }
  if (tid == 0) g_pexp[bi * 16 + bj] = sw[0];
  __syncthreads();
  sw[tid] = dacc;
  __syncthreads();
  for (int s = 128; s > 0; s >>= 1) {
    if (tid < s) sw[tid] += sw[tid + s];
    __syncthreads();
  }
  if (tid == 0) g_pdiag[bi * 16 + bj] = sw[0];
}

// ---------------- finalize ----------------
__global__ void __launch_bounds__(256) finalize_kernel(float* out, int out_size)
{
  __shared__ float se[256];
  __shared__ float sd[256];
  const int tid = threadIdx.x;
  se[tid] = g_pexp[tid] + g_pexp[tid + 256];
  sd[tid] = g_pdiag[tid] + g_pdiag[tid + 256];
  __syncthreads();
  for (int s = 128; s > 0; s >>= 1) {
    if (tid < s) { se[tid] += se[tid + s]; sd[tid] += sd[tid + s]; }
    __syncthreads();
  }
  if (tid == 0)
    out[0] = sd[0] * (1.0f / NPTS) - se[0] * (1.0f / ((float)NPTS * (float)NPTS));
  for (int t = tid; t < out_size; t += 256)
    if (t > 0) out[t] = 0.0f;
}

extern "C" void kernel_launch(void* const* d_in, const int* in_sizes, int n_in,
                              void* d_out, int out_size)
{
  const float* x  = (const float*)d_in[0];
  const float* y  = (const float*)d_in[1];
  const float* W1 = (const float*)d_in[2];
  const float* b1 = (const float*)d_in[3];
  const float* W2 = (const float*)d_in[4];
  const float* b2 = (const float*)d_in[5];

  cudaFuncSetAttribute(pair_kernel, cudaFuncAttributeMaxDynamicSharedMemorySize, SMEM_BYTES);

  prologue_kernel<<<dim3(64, 2), 256>>>(x, y, W1, b1);
  pair_kernel<<<dim3(16, 32), 256, SMEM_BYTES>>>(W2, b2);
  finalize_kernel<<<1, 256>>>((float*)d_out, out_size);
}